// round 2
// baseline (speedup 1.0000x reference)
#include <cuda_runtime.h>

#define BB 8
#define CC 64
#define NN 4096
#define KK 16
#define EE 64
#define NPOINTS (BB*NN)            // 32768
#define CNT1 524288.0f             // B*N*K
#define CNT3 32768.0f              // B*N
#define EPSV 1e-5f

typedef unsigned long long u64;

// Scratch (device globals: allocation-free rule)
__device__ float g_y1t[NPOINTS*EE];       // 8 MB   y1 transposed: [b*N+n][e]
__device__ float g_zmax[NPOINTS*EE];      // 8 MB   max_k of pre-BN layer-2 z
__device__ float g_zmin[NPOINTS*EE];      // 8 MB   min_k of pre-BN layer-2 z
__device__ float g_sum1[EE], g_sumsq1[EE];
__device__ float g_sum2[EE], g_sumsq2[EE];
__device__ float g_sum3[EE], g_sumsq3[EE];

__device__ __forceinline__ u64 ffma2(u64 a, u64 b, u64 c) {
    u64 d;
    asm("fma.rn.f32x2 %0, %1, %2, %3;" : "=l"(d) : "l"(a), "l"(b), "l"(c));
    return d;
}
__device__ __forceinline__ u64 faddf2(u64 a, u64 b) {
    u64 d;
    asm("add.rn.f32x2 %0, %1, %2;" : "=l"(d) : "l"(a), "l"(b));
    return d;
}
__device__ __forceinline__ float2 unpack2(u64 v) {
    float2 r;
    asm("mov.b64 {%0, %1}, %2;" : "=f"(r.x), "=f"(r.y) : "l"(v));
    return r;
}

// y1t[b][n][e] = sum_c W1[e][c] * x[b][c][n];  block(0,0) also zeroes accumulators
__global__ void k_y1(const float* __restrict__ x, const float* __restrict__ W1) {
    __shared__ float xs[CC][64];
    __shared__ float W1sT[CC][EE];
    int b = blockIdx.y;
    int n0 = blockIdx.x * 64;
    int t = threadIdx.x;
    if (blockIdx.x == 0 && blockIdx.y == 0 && t < EE) {
        g_sum1[t]=0.f; g_sumsq1[t]=0.f;
        g_sum2[t]=0.f; g_sumsq2[t]=0.f;
        g_sum3[t]=0.f; g_sumsq3[t]=0.f;
    }
    for (int i = t; i < CC*EE; i += 256) {
        int o = i >> 6, c = i & 63;
        W1sT[c][o] = W1[i];
    }
    for (int i = t; i < CC*64; i += 256) {
        int c = i >> 6, j = i & 63;
        xs[c][j] = x[(b*CC + c)*NN + n0 + j];
    }
    __syncthreads();
    int e = t & 63;
    int nb = (t >> 6) * 16;
    float acc[16];
    #pragma unroll
    for (int i = 0; i < 16; i++) acc[i] = 0.f;
    #pragma unroll 4
    for (int c = 0; c < CC; c++) {
        float w = W1sT[c][e];
        #pragma unroll
        for (int i = 0; i < 16; i++) acc[i] = fmaf(w, xs[c][nb+i], acc[i]);
    }
    #pragma unroll
    for (int i = 0; i < 16; i++)
        g_y1t[(b*NN + n0 + nb + i)*EE + e] = acc[i];
}

// BN1 stats: per-channel sum / sumsq of d = y1t[j] - y1t[n] over all (b,n,k)
__global__ void k_stats1(const int* __restrict__ idx) {
    __shared__ float red[4][64];
    int t = threadIdx.x;
    int c = t & 63, g = t >> 6;
    float s = 0.f, q = 0.f;
    int p0 = blockIdx.x * 64;
    for (int pl = g; pl < 64; pl += 4) {
        int point = p0 + pl;
        int brow = (point >> 12) << 12;
        float yn = g_y1t[point*EE + c];
        const int* ip = idx + point*KK;
        #pragma unroll
        for (int k = 0; k < KK; k++) {
            int j = ip[k];
            float yj = g_y1t[(brow + j)*EE + c];
            float d = yj - yn;
            s += d;
            q = fmaf(d, d, q);
        }
    }
    red[g][c] = s;
    __syncthreads();
    if (g == 0) atomicAdd(&g_sum1[c], red[0][c]+red[1][c]+red[2][c]+red[3][c]);
    __syncthreads();
    red[g][c] = q;
    __syncthreads();
    if (g == 0) atomicAdd(&g_sumsq1[c], red[0][c]+red[1][c]+red[2][c]+red[3][c]);
}

// Main pass: h1 = relu(a1*(y_j - y_n)+c1); z = W2@h1; track max_k/min_k; BN2 stats.
// BN1 fold (a1,c1) recomputed inline per thread (cheap, removes a launch).
__global__ void __launch_bounds__(64) k_main1(const int* __restrict__ idx,
                                              const float* __restrict__ W2,
                                              const float* __restrict__ g1,
                                              const float* __restrict__ be1) {
    __shared__ __align__(16) float h1s[KK][EE];
    int t = threadIdx.x;
    u64 w2[32];
    const u64* Wv = (const u64*)(W2 + t*CC);
    #pragma unroll
    for (int q = 0; q < 32; q++) w2[q] = Wv[q];

    float m1 = g_sum1[t] * (1.f/CNT1);
    float v1 = fmaxf(g_sumsq1[t] * (1.f/CNT1) - m1*m1, 0.f);
    float a1t = g1[t] * rsqrtf(v1 + EPSV);
    float c1t = be1[t] - a1t * m1;

    float sz = 0.f, szq = 0.f;
    int p0 = blockIdx.x * 16;
    for (int p = 0; p < 16; p++) {
        int point = p0 + p;
        int brow = (point >> 12) << 12;
        float yn = g_y1t[point*EE + t];
        const int* ip = idx + point*KK;
        #pragma unroll
        for (int k = 0; k < KK; k++) {
            int j = ip[k];
            float yj = g_y1t[(brow + j)*EE + t];
            h1s[k][t] = fmaxf(fmaf(a1t, yj - yn, c1t), 0.f);
        }
        __syncthreads();
        float zmx = -1e30f, zmn = 1e30f;
        #pragma unroll
        for (int k = 0; k < KK; k++) {
            const u64* h2 = (const u64*)(&h1s[k][0]);
            u64 a0 = 0ull, a1p = 0ull;
            #pragma unroll
            for (int q = 0; q < 32; q += 2) {
                a0  = ffma2(w2[q],   h2[q],   a0);
                a1p = ffma2(w2[q+1], h2[q+1], a1p);
            }
            float2 f = unpack2(faddf2(a0, a1p));
            float z = f.x + f.y;
            zmx = fmaxf(zmx, z);
            zmn = fminf(zmn, z);
            sz += z;
            szq = fmaf(z, z, szq);
        }
        g_zmax[point*EE + t] = zmx;
        g_zmin[point*EE + t] = zmn;
        __syncthreads();
    }
    atomicAdd(&g_sum2[t], sz);
    atomicAdd(&g_sumsq2[t], szq);
}

// pooled m = relu(a2*z_sel+c2) (monotone: zmax if a2>=0 else zmin); z3 = W3@m -> out;
// BN3 stats accumulated via warp reduce + atomics. BN2 fold inline.
__global__ void k_pool3(const float* __restrict__ W3,
                        const float* __restrict__ g2,
                        const float* __restrict__ be2,
                        float* __restrict__ out) {
    __shared__ float ms[64][65];
    __shared__ float W3sT[CC][EE];
    int b = blockIdx.y;
    int n0 = blockIdx.x * 64;
    int t = threadIdx.x;
    for (int i = t; i < CC*EE; i += 256) {
        int o = i >> 6, c = i & 63;
        W3sT[c][o] = W3[i];
    }
    {
        int o = t & 63;
        int ng = t >> 6;
        float m2 = g_sum2[o] * (1.f/CNT1);
        float v2 = fmaxf(g_sumsq2[o] * (1.f/CNT1) - m2*m2, 0.f);
        float a2o = g2[o] * rsqrtf(v2 + EPSV);
        float c2o = be2[o] - a2o * m2;
        const float* zsel = (a2o >= 0.f) ? g_zmax : g_zmin;
        for (int nl = ng; nl < 64; nl += 4) {
            int point = b*NN + n0 + nl;
            float zm = zsel[point*EE + o];
            ms[nl][o] = fmaxf(fmaf(a2o, zm, c2o), 0.f);
        }
    }
    __syncthreads();
    int nl = t & 63;
    int ob = (t >> 6) * 16;
    float acc[16];
    #pragma unroll
    for (int i = 0; i < 16; i++) acc[i] = 0.f;
    #pragma unroll 4
    for (int c = 0; c < CC; c++) {
        float mv = ms[nl][c];
        #pragma unroll
        for (int i = 0; i < 16; i++)
            acc[i] = fmaf(W3sT[c][ob+i], mv, acc[i]);
    }
    #pragma unroll
    for (int i = 0; i < 16; i++)
        out[(b*EE + ob + i)*NN + n0 + nl] = acc[i];
    // BN3 stats: warp-reduce (all lanes in a warp share ob) then lane0 atomics
    #pragma unroll
    for (int i = 0; i < 16; i++) {
        float s = acc[i];
        float q = acc[i] * acc[i];
        #pragma unroll
        for (int off = 16; off > 0; off >>= 1) {
            s += __shfl_xor_sync(0xffffffffu, s, off);
            q += __shfl_xor_sync(0xffffffffu, q, off);
        }
        if ((t & 31) == 0) {
            atomicAdd(&g_sum3[ob + i], s);
            atomicAdd(&g_sumsq3[ob + i], q);
        }
    }
}

// In-place BN3 + ReLU (BN3 fold computed once per block into shared)
__global__ void k_out(const float* __restrict__ g3, const float* __restrict__ be3,
                      float* __restrict__ out) {
    __shared__ float sa[EE], sc[EE];
    int t = threadIdx.x;
    if (t < EE) {
        float m3 = g_sum3[t] * (1.f/CNT3);
        float v3 = fmaxf(g_sumsq3[t] * (1.f/CNT3) - m3*m3, 0.f);
        float a3 = g3[t] * rsqrtf(v3 + EPSV);
        sa[t] = a3;
        sc[t] = be3[t] - a3 * m3;
    }
    __syncthreads();
    int gi = blockIdx.x * blockDim.x + t;       // float4 index, 524288 total
    int o = (gi >> 10) & 63;                    // 1024 float4 per (b,o) row
    float4* out4 = (float4*)out;
    float4 v = out4[gi];
    float a = sa[o], c = sc[o];
    v.x = fmaxf(fmaf(a, v.x, c), 0.f);
    v.y = fmaxf(fmaf(a, v.y, c), 0.f);
    v.z = fmaxf(fmaf(a, v.z, c), 0.f);
    v.w = fmaxf(fmaf(a, v.w, c), 0.f);
    out4[gi] = v;
}

extern "C" void kernel_launch(void* const* d_in, const int* in_sizes, int n_in,
                              void* d_out, int out_size) {
    const float* x   = (const float*)d_in[0];
    const int*   idx = (const int*)  d_in[1];
    const float* W1  = (const float*)d_in[2];
    const float* g1  = (const float*)d_in[4];
    const float* be1 = (const float*)d_in[5];
    const float* W2  = (const float*)d_in[6];
    const float* g2  = (const float*)d_in[8];
    const float* be2 = (const float*)d_in[9];
    const float* W3  = (const float*)d_in[10];
    const float* g3  = (const float*)d_in[12];
    const float* be3 = (const float*)d_in[13];
    float* out = (float*)d_out;

    k_y1    <<<dim3(64, 8), 256>>>(x, W1);
    k_stats1<<<512, 256>>>(idx);
    k_main1 <<<2048, 64>>>(idx, W2, g1, be1);
    k_pool3 <<<dim3(64, 8), 256>>>(W3, g2, be2, out);
    k_out   <<<2048, 256>>>(g3, be3, out);
}

// round 3
// speedup vs baseline: 1.1620x; 1.1620x over previous
#include <cuda_runtime.h>

#define BB 8
#define CC 64
#define NN 4096
#define KK 16
#define EE 64
#define NPOINTS (BB*NN)            // 32768
#define CNT1 524288.0f             // B*N*K
#define CNT3 32768.0f              // B*N
#define EPSV 1e-5f

typedef unsigned long long u64;

// Scratch (device globals: allocation-free rule)
__device__ float g_y1t[NPOINTS*EE];       // 8 MB   y1 transposed: [b*N+n][e]
__device__ float g_zmax[NPOINTS*EE];      // 8 MB   max_k of pre-BN layer-2 z
__device__ float g_zmin[NPOINTS*EE];      // 8 MB   min_k of pre-BN layer-2 z
__device__ float g_sum1[EE], g_sumsq1[EE];
__device__ float g_sum2[EE], g_sumsq2[EE];
__device__ float g_sum3[EE], g_sumsq3[EE];

__device__ __forceinline__ u64 ffma2(u64 a, u64 b, u64 c) {
    u64 d;
    asm("fma.rn.f32x2 %0, %1, %2, %3;" : "=l"(d) : "l"(a), "l"(b), "l"(c));
    return d;
}
__device__ __forceinline__ u64 faddf2(u64 a, u64 b) {
    u64 d;
    asm("add.rn.f32x2 %0, %1, %2;" : "=l"(d) : "l"(a), "l"(b));
    return d;
}
__device__ __forceinline__ float2 unpack2(u64 v) {
    float2 r;
    asm("mov.b64 {%0, %1}, %2;" : "=f"(r.x), "=f"(r.y) : "l"(v));
    return r;
}

// y1t[b][n][e] = sum_c W1[e][c] * x[b][c][n];  block(0,0) also zeroes accumulators
__global__ void k_y1(const float* __restrict__ x, const float* __restrict__ W1) {
    __shared__ float xs[CC][64];
    __shared__ float W1sT[CC][EE];
    int b = blockIdx.y;
    int n0 = blockIdx.x * 64;
    int t = threadIdx.x;
    if (blockIdx.x == 0 && blockIdx.y == 0 && t < EE) {
        g_sum1[t]=0.f; g_sumsq1[t]=0.f;
        g_sum2[t]=0.f; g_sumsq2[t]=0.f;
        g_sum3[t]=0.f; g_sumsq3[t]=0.f;
    }
    for (int i = t; i < CC*EE; i += 256) {
        int o = i >> 6, c = i & 63;
        W1sT[c][o] = W1[i];
    }
    for (int i = t; i < CC*64; i += 256) {
        int c = i >> 6, j = i & 63;
        xs[c][j] = x[(b*CC + c)*NN + n0 + j];
    }
    __syncthreads();
    int e = t & 63;
    int nb = (t >> 6) * 16;
    float acc[16];
    #pragma unroll
    for (int i = 0; i < 16; i++) acc[i] = 0.f;
    #pragma unroll 4
    for (int c = 0; c < CC; c++) {
        float w = W1sT[c][e];
        #pragma unroll
        for (int i = 0; i < 16; i++) acc[i] = fmaf(w, xs[c][nb+i], acc[i]);
    }
    #pragma unroll
    for (int i = 0; i < 16; i++)
        g_y1t[(b*NN + n0 + nb + i)*EE + e] = acc[i];
}

// BN1 stats: per-channel sum / sumsq of d = y1t[j] - y1t[n] over all (b,n,k)
__global__ void k_stats1(const int* __restrict__ idx) {
    __shared__ float red[4][64];
    int t = threadIdx.x;
    int c = t & 63, g = t >> 6;
    float s = 0.f, q = 0.f;
    int p0 = blockIdx.x * 64;
    for (int pl = g; pl < 64; pl += 4) {
        int point = p0 + pl;
        int brow = (point >> 12) << 12;
        float yn = g_y1t[point*EE + c];
        const int* ip = idx + point*KK;
        #pragma unroll
        for (int k = 0; k < KK; k++) {
            int j = ip[k];
            float yj = g_y1t[(brow + j)*EE + c];
            float d = yj - yn;
            s += d;
            q = fmaf(d, d, q);
        }
    }
    red[g][c] = s;
    __syncthreads();
    if (g == 0) atomicAdd(&g_sum1[c], red[0][c]+red[1][c]+red[2][c]+red[3][c]);
    __syncthreads();
    red[g][c] = q;
    __syncthreads();
    if (g == 0) atomicAdd(&g_sumsq1[c], red[0][c]+red[1][c]+red[2][c]+red[3][c]);
}

// Main pass: h1 = relu(a1*(y_j - y_n)+c1); z = W2@h1; track max_k/min_k; BN2 stats.
// Dot products via packed fma.rn.f32x2 with LDS.128 (ulonglong2) shared loads.
__global__ void __launch_bounds__(64) k_main1(const int* __restrict__ idx,
                                              const float* __restrict__ W2,
                                              const float* __restrict__ g1,
                                              const float* __restrict__ be1) {
    __shared__ __align__(16) float h1s[KK][EE];
    int t = threadIdx.x;
    u64 w2[32];
    const ulonglong2* Wv = (const ulonglong2*)(W2 + t*CC);
    #pragma unroll
    for (int q = 0; q < 16; q++) {
        ulonglong2 w = Wv[q];
        w2[2*q]   = w.x;
        w2[2*q+1] = w.y;
    }

    float m1 = g_sum1[t] * (1.f/CNT1);
    float v1 = fmaxf(g_sumsq1[t] * (1.f/CNT1) - m1*m1, 0.f);
    float a1t = g1[t] * rsqrtf(v1 + EPSV);
    float c1t = be1[t] - a1t * m1;

    float sz = 0.f, szq = 0.f;
    int p0 = blockIdx.x * 16;
    for (int p = 0; p < 16; p++) {
        int point = p0 + p;
        int brow = (point >> 12) << 12;
        float yn = g_y1t[point*EE + t];
        const int* ip = idx + point*KK;
        #pragma unroll
        for (int k = 0; k < KK; k++) {
            int j = ip[k];
            float yj = g_y1t[(brow + j)*EE + t];
            h1s[k][t] = fmaxf(fmaf(a1t, yj - yn, c1t), 0.f);
        }
        __syncthreads();
        float zmx = -1e30f, zmn = 1e30f;
        #pragma unroll
        for (int k = 0; k < KK; k++) {
            const ulonglong2* h2 = (const ulonglong2*)(&h1s[k][0]);
            u64 a0 = 0ull, a1p = 0ull;
            #pragma unroll
            for (int q = 0; q < 16; q++) {
                ulonglong2 hv = h2[q];
                a0  = ffma2(w2[2*q],   hv.x, a0);
                a1p = ffma2(w2[2*q+1], hv.y, a1p);
            }
            float2 f = unpack2(faddf2(a0, a1p));
            float z = f.x + f.y;
            zmx = fmaxf(zmx, z);
            zmn = fminf(zmn, z);
            sz += z;
            szq = fmaf(z, z, szq);
        }
        g_zmax[point*EE + t] = zmx;
        g_zmin[point*EE + t] = zmn;
        __syncthreads();
    }
    atomicAdd(&g_sum2[t], sz);
    atomicAdd(&g_sumsq2[t], szq);
}

// pooled m = relu(a2*z_sel+c2) (monotone: zmax if a2>=0 else zmin); z3 = W3@m -> out
__global__ void k_pool3(const float* __restrict__ W3,
                        const float* __restrict__ g2,
                        const float* __restrict__ be2,
                        float* __restrict__ out) {
    __shared__ float ms[64][65];
    __shared__ float W3sT[CC][EE];
    int b = blockIdx.y;
    int n0 = blockIdx.x * 64;
    int t = threadIdx.x;
    for (int i = t; i < CC*EE; i += 256) {
        int o = i >> 6, c = i & 63;
        W3sT[c][o] = W3[i];
    }
    {
        int o = t & 63;
        int ng = t >> 6;
        float m2 = g_sum2[o] * (1.f/CNT1);
        float v2 = fmaxf(g_sumsq2[o] * (1.f/CNT1) - m2*m2, 0.f);
        float a2o = g2[o] * rsqrtf(v2 + EPSV);
        float c2o = be2[o] - a2o * m2;
        const float* zsel = (a2o >= 0.f) ? g_zmax : g_zmin;
        for (int nl = ng; nl < 64; nl += 4) {
            int point = b*NN + n0 + nl;
            float zm = zsel[point*EE + o];
            ms[nl][o] = fmaxf(fmaf(a2o, zm, c2o), 0.f);
        }
    }
    __syncthreads();
    int nl = t & 63;
    int ob = (t >> 6) * 16;
    float acc[16];
    #pragma unroll
    for (int i = 0; i < 16; i++) acc[i] = 0.f;
    #pragma unroll 4
    for (int c = 0; c < CC; c++) {
        float mv = ms[nl][c];
        #pragma unroll
        for (int i = 0; i < 16; i++)
            acc[i] = fmaf(W3sT[c][ob+i], mv, acc[i]);
    }
    #pragma unroll
    for (int i = 0; i < 16; i++)
        out[(b*EE + ob + i)*NN + n0 + nl] = acc[i];
}

// BN3 stats: one CTA per (b,o) plane of out (holds pre-BN z3)
__global__ void k_stats3(const float* __restrict__ out) {
    __shared__ float r1[256], r2[256];
    int p = blockIdx.x;        // p = b*64 + o
    int o = p & 63;
    const float* base = out + (size_t)p*NN;
    int t = threadIdx.x;
    float s = 0.f, q = 0.f;
    for (int i = t; i < NN; i += 256) {
        float v = base[i];
        s += v;
        q = fmaf(v, v, q);
    }
    r1[t] = s; r2[t] = q;
    __syncthreads();
    for (int w = 128; w > 0; w >>= 1) {
        if (t < w) { r1[t] += r1[t+w]; r2[t] += r2[t+w]; }
        __syncthreads();
    }
    if (t == 0) {
        atomicAdd(&g_sum3[o], r1[0]);
        atomicAdd(&g_sumsq3[o], r2[0]);
    }
}

// In-place BN3 + ReLU (BN3 fold computed once per block into shared)
__global__ void k_out(const float* __restrict__ g3, const float* __restrict__ be3,
                      float* __restrict__ out) {
    __shared__ float sa[EE], sc[EE];
    int t = threadIdx.x;
    if (t < EE) {
        float m3 = g_sum3[t] * (1.f/CNT3);
        float v3 = fmaxf(g_sumsq3[t] * (1.f/CNT3) - m3*m3, 0.f);
        float a3 = g3[t] * rsqrtf(v3 + EPSV);
        sa[t] = a3;
        sc[t] = be3[t] - a3 * m3;
    }
    __syncthreads();
    int gi = blockIdx.x * blockDim.x + t;       // float4 index, 524288 total
    int o = (gi >> 10) & 63;                    // 1024 float4 per (b,o) row
    float4* out4 = (float4*)out;
    float4 v = out4[gi];
    float a = sa[o], c = sc[o];
    v.x = fmaxf(fmaf(a, v.x, c), 0.f);
    v.y = fmaxf(fmaf(a, v.y, c), 0.f);
    v.z = fmaxf(fmaf(a, v.z, c), 0.f);
    v.w = fmaxf(fmaf(a, v.w, c), 0.f);
    out4[gi] = v;
}

extern "C" void kernel_launch(void* const* d_in, const int* in_sizes, int n_in,
                              void* d_out, int out_size) {
    const float* x   = (const float*)d_in[0];
    const int*   idx = (const int*)  d_in[1];
    const float* W1  = (const float*)d_in[2];
    const float* g1  = (const float*)d_in[4];
    const float* be1 = (const float*)d_in[5];
    const float* W2  = (const float*)d_in[6];
    const float* g2  = (const float*)d_in[8];
    const float* be2 = (const float*)d_in[9];
    const float* W3  = (const float*)d_in[10];
    const float* g3  = (const float*)d_in[12];
    const float* be3 = (const float*)d_in[13];
    float* out = (float*)d_out;

    k_y1    <<<dim3(64, 8), 256>>>(x, W1);
    k_stats1<<<512, 256>>>(idx);
    k_main1 <<<2048, 64>>>(idx, W2, g1, be1);
    k_pool3 <<<dim3(64, 8), 256>>>(W3, g2, be2, out);
    k_stats3<<<512, 256>>>(out);
    k_out   <<<2048, 256>>>(g3, be3, out);
}